// round 8
// baseline (speedup 1.0000x reference)
#include <cuda_runtime.h>
#include <cuda_bf16.h>

// Problem constants
#define BB 4
#define PP 64
#define SS 8
#define YD 16
#define GD 48
#define NOUT (BB*PP*PP*SS*SS)          // 1,048,576 outputs

#define WARPS_PER_BLOCK 8

__device__ __forceinline__ float dot4(float4 v, float4 w) {
    return fmaf(v.x, w.x, fmaf(v.y, w.y, fmaf(v.z, w.z, v.w * w.w)));
}

// ---------------------------------------------------------------------------
// Single kernel. Each warp = 32 consecutive outputs = one 6KB tile of g.
// Hot loop is byte-identical to the proven R2 schedule (32 regs, 6 loads in
// flight):
//   - 2 batches x 6 coalesced LDG.128 (lane l -> float4 f = l + 32k)
//   - weight column f%12 = (l%12+8k)%12 cycles {A,B,C}: 3 register float4s
//   - per-lane partial -> smem (conflict-free STS.32)
//   - lane r sums its 12 partials via 3 conflict-free LDS.128
// Epilogue (all streaming registers dead -> pure register reuse):
//   - per-lane c1 = y[b,j,sj,:]·Wy[0:16], c2 = y[b,i,si,:]·Wy[16:32]
//     (8 L1-resident LDG.128 + 8 uniform Wy loads + 8 dot4; no shuffles,
//      no smem, no extra kernel)
// ---------------------------------------------------------------------------
__global__ __launch_bounds__(32 * WARPS_PER_BLOCK)
void fused_kernel(const float* __restrict__ y,
                  const float* __restrict__ g,
                  const float* __restrict__ Wy,
                  const float* __restrict__ by,
                  const float* __restrict__ Wg,
                  const float* __restrict__ bg,
                  float* __restrict__ out) {
    __shared__ float part[WARPS_PER_BLOCK][12 * 32];

    const int lane = threadIdx.x & 31;
    const int wIn  = threadIdx.x >> 5;
    const int warp = blockIdx.x * WARPS_PER_BLOCK + wIn;
    const int base = warp * 32;

    // The 3 weight columns this lane ever needs (k%3 == 0,1,2 -> A,B,C)
    const int l12 = lane % 12;
    int cB = l12 + 8; if (cB >= 12) cB -= 12;
    int cC = l12 + 4; if (cC >= 12) cC -= 12;
    const float4* wv = (const float4*)Wg;
    const float4 wA = __ldg(wv + l12);
    const float4 wB = __ldg(wv + cB);
    const float4 wC = __ldg(wv + cC);

    const float4* gs = (const float4*)(g + (size_t)base * GD);
    float* p = part[wIn];

    // ---- batch 1: k = 0..5 (6 loads in flight) ----
    float4 v0 = __ldcs(gs + lane +   0);
    float4 v1 = __ldcs(gs + lane +  32);
    float4 v2 = __ldcs(gs + lane +  64);
    float4 v3 = __ldcs(gs + lane +  96);
    float4 v4 = __ldcs(gs + lane + 128);
    float4 v5 = __ldcs(gs + lane + 160);
    p[lane +   0] = dot4(v0, wA);
    p[lane +  32] = dot4(v1, wB);
    p[lane +  64] = dot4(v2, wC);
    p[lane +  96] = dot4(v3, wA);
    p[lane + 128] = dot4(v4, wB);
    p[lane + 160] = dot4(v5, wC);

    // ---- batch 2: k = 6..11 ----
    float4 u0 = __ldcs(gs + lane + 192);
    float4 u1 = __ldcs(gs + lane + 224);
    float4 u2 = __ldcs(gs + lane + 256);
    float4 u3 = __ldcs(gs + lane + 288);
    float4 u4 = __ldcs(gs + lane + 320);
    float4 u5 = __ldcs(gs + lane + 352);
    p[lane + 192] = dot4(u0, wA);
    p[lane + 224] = dot4(u1, wB);
    p[lane + 256] = dot4(u2, wC);
    p[lane + 288] = dot4(u3, wA);
    p[lane + 320] = dot4(u4, wB);
    p[lane + 352] = dot4(u5, wC);

    __syncwarp();

    // ---- reduce: lane r owns output base+r, partials at p[12r .. 12r+11] ----
    const float4* pr = (const float4*)(p + lane * 12);   // 48B aligned
    float4 t0 = pr[0], t1 = pr[1], t2 = pr[2];
    float sum = ((t0.x + t0.y) + (t0.z + t0.w))
              + ((t1.x + t1.y) + (t1.z + t1.w))
              + ((t2.x + t2.y) + (t2.z + t2.w));

    // ---- epilogue: per-lane broadcast terms (streaming regs all dead) ----
    // o = ((((b*P+i)*P+j)*S+si)*S+sj)
    const int o  = base + lane;
    const int sj = o & 7;
    const int si = (o >> 3) & 7;
    const int j  = (o >> 6) & 63;
    const int i  = (o >> 12) & 63;
    const int b  = o >> 18;

    const float4* yj = (const float4*)y + (size_t)((((b << 6) + j) << 3) + sj) * 4;
    const float4* yi = (const float4*)y + (size_t)((((b << 6) + i) << 3) + si) * 4;
    const float4* w1 = (const float4*)Wy;          // Wy[0:16]
    const float4* w2 = (const float4*)(Wy + YD);   // Wy[16:32]

    float c = __ldg(by) + __ldg(bg);
    c += dot4(__ldg(yj + 0), __ldg(w1 + 0));
    c += dot4(__ldg(yj + 1), __ldg(w1 + 1));
    c += dot4(__ldg(yj + 2), __ldg(w1 + 2));
    c += dot4(__ldg(yj + 3), __ldg(w1 + 3));
    c += dot4(__ldg(yi + 0), __ldg(w2 + 0));
    c += dot4(__ldg(yi + 1), __ldg(w2 + 1));
    c += dot4(__ldg(yi + 2), __ldg(w2 + 2));
    c += dot4(__ldg(yi + 3), __ldg(w2 + 3));

    __stcs(out + o, sum + c);
}

// ---------------------------------------------------------------------------
// Launch
// inputs (metadata order): y(32768), pairwise_g(50331648), Wy(32), by(1),
//                          Wg(48), bg(1)
// ---------------------------------------------------------------------------
extern "C" void kernel_launch(void* const* d_in, const int* in_sizes, int n_in,
                              void* d_out, int out_size) {
    const float* y  = (const float*)d_in[0];
    const float* g  = (const float*)d_in[1];
    const float* Wy = (const float*)d_in[2];
    const float* by = (const float*)d_in[3];
    const float* Wg = (const float*)d_in[4];
    const float* bg = (const float*)d_in[5];
    float* out = (float*)d_out;

    const int tiles  = NOUT / 32;                 // 32768 warps
    const int blocks = tiles / WARPS_PER_BLOCK;   // 4096
    fused_kernel<<<blocks, 32 * WARPS_PER_BLOCK>>>(y, g, Wy, by, Wg, bg, out);
}

// round 9
// speedup vs baseline: 1.1728x; 1.1728x over previous
#include <cuda_runtime.h>
#include <cuda_bf16.h>

// Problem constants
#define BB 4
#define PP 64
#define SS 8
#define YD 16
#define GD 48
#define NOUT (BB*PP*PP*SS*SS)          // 1,048,576 outputs

#define WARPS_PER_BLOCK 8              // 256 threads = 256 consecutive outputs

__device__ __forceinline__ float dot4(float4 v, float4 w) {
    return fmaf(v.x, w.x, fmaf(v.y, w.y, fmaf(v.z, w.z, v.w * w.w)));
}

// ---------------------------------------------------------------------------
// Fused kernel. Block = 256 consecutive outputs: (b,i) fixed, j spans 4
// values, (si,sj) full.
//
// Prologue (STRICTLY before any g load, so its registers are dead at the
// barrier and the hot loop compiles to R2's proven 32-reg schedule):
//   threads 0..39 build sc1[4][8] = y[b,j0+jj,s,:]·Wy[0:16]+bias and
//   sc2[8] = y[b,i,s,:]·Wy[16:32] in smem; one __syncthreads.
//
// Hot loop (identical to R2): per warp one 6KB g tile,
//   - 2 batches x 6 coalesced LDG.128 (lane l -> float4 f = l + 32k)
//   - weight column f%12 = (l%12+8k)%12 cycles {A,B,C}: 3 register float4s
//   - per-lane partial -> smem (conflict-free STS.32)
//   - lane r sums its 12 partials via 3 conflict-free LDS.128
//   - + sc1[jj][sj] + sc2[si] (broadcast LDS)
// ---------------------------------------------------------------------------
__global__ __launch_bounds__(32 * WARPS_PER_BLOCK)
void fused_kernel(const float* __restrict__ y,
                  const float* __restrict__ g,
                  const float* __restrict__ Wy,
                  const float* __restrict__ by,
                  const float* __restrict__ Wg,
                  const float* __restrict__ bg,
                  float* __restrict__ out) {
    __shared__ float part[WARPS_PER_BLOCK][12 * 32];
    __shared__ float sc1[4 * SS];      // c1[jj][s] (+bias)
    __shared__ float sc2[SS];          // c2[s]

    const int tid  = threadIdx.x;
    const int lane = tid & 31;
    const int wIn  = tid >> 5;
    const int blockBase = blockIdx.x * 256;

    // ---- per-block broadcast tables: fully before any streaming load ----
    if (tid < 40) {
        const int b  =  blockBase >> 18;
        const int i  = (blockBase >> 12) & 63;
        const int j0 = (blockBase >> 6)  & 63;       // low 2 bits are 0
        int row, woff;
        if (tid < 32) {                              // sc1: jj = tid>>3, s = tid&7
            row  = ((b << 6) + j0 + (tid >> 3)) * SS + (tid & 7);
            woff = 0;
        } else {                                     // sc2: s = tid-32
            row  = ((b << 6) + i) * SS + (tid - 32);
            woff = YD;
        }
        const float4* yr = (const float4*)(y + (size_t)row * YD);
        const float4* wr = (const float4*)(Wy + woff);
        float d = dot4(__ldg(yr + 0), __ldg(wr + 0))
                + dot4(__ldg(yr + 1), __ldg(wr + 1))
                + dot4(__ldg(yr + 2), __ldg(wr + 2))
                + dot4(__ldg(yr + 3), __ldg(wr + 3));
        if (tid < 32) sc1[tid] = d + __ldg(by) + __ldg(bg);
        else          sc2[tid - 32] = d;
    }
    __syncthreads();                    // prologue registers die here

    // ---- per-lane weight columns: (lane%12 + {0,8,4}) % 12 ----
    const int l12 = lane % 12;
    int cB = l12 + 8; if (cB >= 12) cB -= 12;
    int cC = l12 + 4; if (cC >= 12) cC -= 12;
    const float4* wv = (const float4*)Wg;
    const float4 wA = __ldg(wv + l12);
    const float4 wB = __ldg(wv + cB);
    const float4 wC = __ldg(wv + cC);

    const int base = blockBase + wIn * 32;
    const float4* gs = (const float4*)(g + (size_t)base * GD);
    float* p = part[wIn];

    // ---- batch 1: k = 0..5 (6 loads in flight) ----
    float4 v0 = __ldcs(gs + lane +   0);
    float4 v1 = __ldcs(gs + lane +  32);
    float4 v2 = __ldcs(gs + lane +  64);
    float4 v3 = __ldcs(gs + lane +  96);
    float4 v4 = __ldcs(gs + lane + 128);
    float4 v5 = __ldcs(gs + lane + 160);
    p[lane +   0] = dot4(v0, wA);
    p[lane +  32] = dot4(v1, wB);
    p[lane +  64] = dot4(v2, wC);
    p[lane +  96] = dot4(v3, wA);
    p[lane + 128] = dot4(v4, wB);
    p[lane + 160] = dot4(v5, wC);

    // ---- batch 2: k = 6..11 ----
    float4 u0 = __ldcs(gs + lane + 192);
    float4 u1 = __ldcs(gs + lane + 224);
    float4 u2 = __ldcs(gs + lane + 256);
    float4 u3 = __ldcs(gs + lane + 288);
    float4 u4 = __ldcs(gs + lane + 320);
    float4 u5 = __ldcs(gs + lane + 352);
    p[lane + 192] = dot4(u0, wA);
    p[lane + 224] = dot4(u1, wB);
    p[lane + 256] = dot4(u2, wC);
    p[lane + 288] = dot4(u3, wA);
    p[lane + 320] = dot4(u4, wB);
    p[lane + 352] = dot4(u5, wC);

    __syncwarp();

    // ---- reduce: lane r owns output base+r, partials at p[12r .. 12r+11] ----
    const float4* pr = (const float4*)(p + lane * 12);   // 48B aligned
    float4 t0 = pr[0], t1 = pr[1], t2 = pr[2];
    float sum = ((t0.x + t0.y) + (t0.z + t0.w))
              + ((t1.x + t1.y) + (t1.z + t1.w))
              + ((t2.x + t2.y) + (t2.z + t2.w));

    // broadcast terms: warp's jj = wIn>>1, si0 = (wIn&1)*4
    sum += sc1[((wIn >> 1) << 3) + (lane & 7)];
    sum += sc2[((wIn & 1) << 2) + (lane >> 3)];

    __stcs(out + base + lane, sum);
}

// ---------------------------------------------------------------------------
// Launch
// inputs (metadata order): y(32768), pairwise_g(50331648), Wy(32), by(1),
//                          Wg(48), bg(1)
// ---------------------------------------------------------------------------
extern "C" void kernel_launch(void* const* d_in, const int* in_sizes, int n_in,
                              void* d_out, int out_size) {
    const float* y  = (const float*)d_in[0];
    const float* g  = (const float*)d_in[1];
    const float* Wy = (const float*)d_in[2];
    const float* by = (const float*)d_in[3];
    const float* Wg = (const float*)d_in[4];
    const float* bg = (const float*)d_in[5];
    float* out = (float*)d_out;

    const int blocks = NOUT / 256;                // 4096
    fused_kernel<<<blocks, 32 * WARPS_PER_BLOCK>>>(y, g, Wy, by, Wg, bg, out);
}